// round 16
// baseline (speedup 1.0000x reference)
#include <cuda_runtime.h>
#include <mma.h>
#include <cstdint>

using namespace nvcuda;

// Problem constants
#define BQ    4
#define CCH   2
#define SLEN  4096
#define OUTC  512
#define TDIM  72
#define NT    80          // padded t-range per batch (5 x 16)
#define KCH   32          // split-K chunks of 128 k each
#define KTILE 16          // k per cp.async staging tile
#define NTILES 8

// ---- device scratch (no allocations allowed) ----
__device__ float g_Whi[OUTC * 4096];              // tf32-valued weights (8 MB)
__device__ float g_Tpart[KCH * BQ * OUTC * NT];   // [ks][b][o][t80]  21 MB
__device__ float g_swT[2048];                     // transposed stft: [m*32 + l]

// ---- smem layout for mma kernel (float offsets) ----
#define XS_LEN  336       // raw x window: 2*127 + 79 = 333, padded
#define A_LDM   16        // no pad: 64 B rows (cp.async 16B-aligned)
#define B_LDM   20
#define MROWS   256
#define A_BUF   (MROWS * A_LDM)     // 4096 floats per stage
#define B_BUF   (NT * B_LDM)        // 1600 floats per buffer
#define NSTAGE  3
#define OFF_XS  0
#define OFF_A   (OFF_XS + XS_LEN)              // 3 stages (hi only)
#define OFF_B   (OFF_A + NSTAGE * A_BUF)       // 2 buffers
#define SM_FLOATS (OFF_B + 2 * B_BUF)          // 15824 floats = 63296 B

#define WSPLIT_BLOCKS ((OUTC * 4096) / 1024)   // 2048

// round-to-nearest tf32
__device__ __forceinline__ float rt32(float w) {
    float r;
    asm("cvt.rna.tf32.f32 %0, %1;" : "=f"(r) : "f"(w));
    return r;
}
__device__ __forceinline__ unsigned smem_u32(const void* p) {
    return (unsigned)__cvta_generic_to_shared(p);
}
__device__ __forceinline__ void cp_async16(unsigned dst, const void* src) {
    asm volatile("cp.async.cg.shared.global [%0], [%1], 16;" :: "r"(dst), "l"(src));
}
#define CP_COMMIT()  asm volatile("cp.async.commit_group;")
#define CP_WAIT1()   asm volatile("cp.async.wait_group 1;")

// ============================================================================
// Kernel 0: round conv_w to tf32 values; 8 tail blocks build the transposed
// stft table g_swT[m*32+l] (once, globally).
// ============================================================================
__global__ __launch_bounds__(256)
void wsplit_kernel(const float* __restrict__ w,
                   const float* __restrict__ stft_w) {
    if (blockIdx.x >= WSPLIT_BLOCKS) {
        int i = (blockIdx.x - WSPLIT_BLOCKS) * 256 + threadIdx.x;   // 0..2047
        int l = i >> 6, m = i & 63;
        g_swT[m * 32 + l] = stft_w[i];
        return;
    }
    int i = (blockIdx.x * 256 + threadIdx.x) * 4;
    float4 v = *(const float4*)(w + i);
    float4 h;
    h.x = rt32(v.x); h.y = rt32(v.y); h.z = rt32(v.z); h.w = rt32(v.w);
    *(float4*)(g_Whi + i) = h;
}

// ============================================================================
// Kernel 1: wmma tf32 split-K GEMM partials (single product: D = Wh * Xh)
//   Tpart[ks][b][o][t] = sum_{k in 128-chunk} Wh[o,k] * Xh[b,ci,2q+t]
// Grid (2 mtile, 4 batch, 32 ks) = 256 CTAs, 256 thr (8 warps), 2 CTA/SM.
// 3-stage cp.async A pipeline + 2-buffer B rotation; ONE barrier per tile.
// [unchanged from R15 — proven at 41.7 µs total]
// ============================================================================
__global__ __launch_bounds__(256, 2)
void mma_kernel(const float* __restrict__ x) {
    extern __shared__ __align__(16) float sm[];
    float* xs = sm + OFF_XS;

    const int tid = threadIdx.x, wid = tid >> 5;
    const int mtile = blockIdx.x;           // 0..1
    const int b     = blockIdx.y;           // 0..3
    const int ks    = blockIdx.z;           // 0..31
    const int ci    = ks >> 4;
    const int q0    = (ks & 15) * 128;

    const float* srcH = g_Whi + (size_t)(mtile * MROWS) * 4096 + ks * 128;

    // ---- prologue: cp.async A stages 0 and 1 ----
    #pragma unroll
    for (int pt = 0; pt < 2; pt++) {
        float* AB = sm + OFF_A + pt * A_BUF;
        #pragma unroll
        for (int j = 0; j < 4; j++) {
            int i = tid + j * 256;               // 0..1023
            int r = i >> 2, c4 = (i & 3) * 4;
            cp_async16(smem_u32(AB + r * A_LDM + c4),
                       srcH + (size_t)r * 4096 + pt * KTILE + c4);
        }
        CP_COMMIT();
    }

    // ---- stage raw x window, then build B[0] ----
    const float* xrow = x + (b * CCH + ci) * SLEN;
    for (int j = tid; j < XS_LEN; j += 256) {
        int g = 2 * q0 + j;
        xs[j] = (g < SLEN) ? xrow[g] : 0.0f;
    }
    __syncthreads();   // xs published
    {
        float* B0 = sm + OFF_B;
        #pragma unroll
        for (int j = 0; j < 5; j++) {
            int i = tid + j * 256;               // 0..1279
            int tt = i >> 4, kk = i & 15;
            B0[tt * B_LDM + kk] = rt32(xs[2 * kk + tt]);
        }
    }

    wmma::fragment<wmma::accumulator, 16, 16, 8, float> c[2][5];
    #pragma unroll
    for (int i = 0; i < 2; i++)
        #pragma unroll
        for (int n = 0; n < 5; n++) wmma::fill_fragment(c[i][n], 0.0f);

    #pragma unroll 1
    for (int t = 0; t < NTILES; t++) {
        const int stg  = t % NSTAGE;
        const int bbuf = t & 1;

        CP_WAIT1();        // A[t] staging complete (issuing-thread view)
        __syncthreads();   // publish A[t] + B[t]; all warps past t-1 MMAs

        // issue A[t+2] into stage (t+2)%3 (tile t-1's stage — safe)
        if (t + 2 < NTILES) {
            float* AN = sm + OFF_A + ((t + 2) % NSTAGE) * A_BUF;
            #pragma unroll
            for (int j = 0; j < 4; j++) {
                int i = tid + j * 256;
                int r = i >> 2, c4 = (i & 3) * 4;
                cp_async16(smem_u32(AN + r * A_LDM + c4),
                           srcH + (size_t)r * 4096 + (t + 2) * KTILE + c4);
            }
        }
        CP_COMMIT();       // commit every iteration (wait_group count exact)

        // build B[t+1] into buf (t+1)&1 (tile t-1's buf — safe)
        if (t + 1 < NTILES) {
            float* Bn = sm + OFF_B + ((t + 1) & 1) * B_BUF;
            #pragma unroll
            for (int j = 0; j < 5; j++) {
                int i = tid + j * 256;
                int tt = i >> 4, kk = i & 15;
                Bn[tt * B_LDM + kk] = rt32(xs[2 * ((t + 1) * KTILE + kk) + tt]);
            }
        }

        // ---- MMAs on tile t: D += Wh * Xh ----
        const float* aH = sm + OFF_A + stg * A_BUF + (wid * 32) * A_LDM;
        const float* Bt = sm + OFF_B + bbuf * B_BUF;
        #pragma unroll
        for (int k8 = 0; k8 < KTILE / 8; k8++) {
            wmma::fragment<wmma::matrix_a, 16, 16, 8, wmma::precision::tf32,
                           wmma::row_major> fah0, fah1;
            wmma::load_matrix_sync(fah0, aH + k8 * 8, A_LDM);
            wmma::load_matrix_sync(fah1, aH + 16 * A_LDM + k8 * 8, A_LDM);
            #pragma unroll
            for (int n = 0; n < 5; n++) {
                wmma::fragment<wmma::matrix_b, 16, 16, 8, wmma::precision::tf32,
                               wmma::col_major> fbh;
                wmma::load_matrix_sync(fbh, Bt + n * 16 * B_LDM + k8 * 8, B_LDM);
                wmma::mma_sync(c[0][n], fah0, fbh, c[0][n]);
                wmma::mma_sync(c[1][n], fah1, fbh, c[1][n]);
            }
        }
    }

    // ---- store partials: Tpart[ks][b][o][t80], row-major ldm=80 ----
    float* dst = g_Tpart + (((size_t)ks * BQ + b) * OUTC
                            + mtile * MROWS + wid * 32) * NT;
    #pragma unroll
    for (int i = 0; i < 2; i++)
        #pragma unroll
        for (int n = 0; n < 5; n++)
            wmma::store_matrix_sync(dst + i * 16 * NT + n * 16, c[i][n],
                                    NT, wmma::mem_row_major);
}

// ============================================================================
// Kernel 2: FUSED split-K reduce + epilogue.
// Phase 1: block sums its 4x72 T values over 32 ks partials (coalesced;
// all loads L2 hits on the 21 MB Tpart). Phase 2: proven epilogue math.
//   out[b,o, p*2048 + m*32 + l] = relu( swT[m,l] * T[b,o,p+m] + conv_b[o] )
// ============================================================================
#define BO_PER_BLK 4
__global__ __launch_bounds__(256)
void epilogue_kernel(const float* __restrict__ conv_b,
                     float* __restrict__ out) {
    __shared__ float Ts[BO_PER_BLK * TDIM];     // 288
    __shared__ float biasS[BO_PER_BLK];

    const int bo0 = blockIdx.x * BO_PER_BLK;
    const int b   = bo0 >> 9;
    const int o0  = bo0 & (OUTC - 1);
    const int tid = threadIdx.x;

    // hoisted sw loads (identical for all 4 outputs of this block) — issued
    // first so they overlap the phase-1 reduction
    float4 sw[4];
    int   pm[4];
    #pragma unroll
    for (int it = 0; it < 4; it++) {
        int q  = tid + it * 256;      // quad index; s' = 4*q
        int sp = q * 4;
        int p  = sp >> 11;
        int m  = (sp >> 5) & 63;
        int l0 = sp & 31;
        pm[it] = p + m;
        sw[it] = __ldg((const float4*)&g_swT[m * 32 + l0]);
    }
    if (tid < BO_PER_BLK)
        biasS[tid] = conv_b[o0 + tid];

    // phase 1: split-K reduce for this block's 288 T values
    for (int j = tid; j < BO_PER_BLK * TDIM; j += 256) {
        int jb = j / TDIM, t = j - jb * TDIM;
        const float* src = g_Tpart + ((size_t)b * OUTC + o0 + jb) * NT + t;
        float s = 0.0f;
        #pragma unroll 8
        for (int ks = 0; ks < KCH; ks++)
            s += src[(size_t)ks * (BQ * OUTC * NT)];
        Ts[j] = s;
    }
    __syncthreads();

    // phase 2: expand + relu + store
    #pragma unroll
    for (int jb = 0; jb < BO_PER_BLK; jb++) {
        const float bias = biasS[jb];
        float4* out4 = (float4*)(out + (size_t)(bo0 + jb) * 4096);
        const float* TsRow = &Ts[jb * TDIM];
        #pragma unroll
        for (int it = 0; it < 4; it++) {
            float tv = TsRow[pm[it]];
            float4 r;
            r.x = fmaxf(fmaf(sw[it].x, tv, bias), 0.0f);
            r.y = fmaxf(fmaf(sw[it].y, tv, bias), 0.0f);
            r.z = fmaxf(fmaf(sw[it].z, tv, bias), 0.0f);
            r.w = fmaxf(fmaf(sw[it].w, tv, bias), 0.0f);
            out4[tid + it * 256] = r;
        }
    }
}

// ============================================================================
extern "C" void kernel_launch(void* const* d_in, const int* in_sizes, int n_in,
                              void* d_out, int out_size) {
    const float* x      = nullptr;
    const float* stft_w = nullptr;
    const float* conv_w = nullptr;
    const float* conv_b = nullptr;
    for (int i = 0; i < n_in; i++) {
        switch (in_sizes[i]) {
            case BQ * CCH * SLEN:  x      = (const float*)d_in[i]; break;  // 32768
            case 32 * 64:          stft_w = (const float*)d_in[i]; break;  // 2048
            case OUTC * 4096:      conv_w = (const float*)d_in[i]; break;  // 2097152
            case OUTC:             conv_b = (const float*)d_in[i]; break;  // 512
        }
    }

    static int smem_set = 0;
    if (!smem_set) {
        cudaFuncSetAttribute(mma_kernel,
                             cudaFuncAttributeMaxDynamicSharedMemorySize,
                             SM_FLOATS * 4);
        smem_set = 1;
    }

    wsplit_kernel<<<WSPLIT_BLOCKS + 8, 256>>>(conv_w, stft_w);
    mma_kernel<<<dim3(2, BQ, KCH), 256, SM_FLOATS * 4>>>(x);
    epilogue_kernel<<<(BQ * OUTC) / BO_PER_BLK, 256>>>(conv_b, (float*)d_out);
}

// round 17
// speedup vs baseline: 1.0626x; 1.0626x over previous
#include <cuda_runtime.h>
#include <mma.h>
#include <cstdint>

using namespace nvcuda;

// Problem constants
#define BQ    4
#define CCH   2
#define SLEN  4096
#define OUTC  512
#define TDIM  72
#define NT    80          // padded t-range per batch (5 x 16)
#define KCH   32          // split-K chunks of 128 k each
#define KTILE 16          // k per cp.async staging tile
#define NTILES 8

// ---- device scratch (no allocations allowed) ----
__device__ float g_Tpart[KCH * BQ * OUTC * NT];   // [ks][b][o][t80]  21 MB
__device__ float g_swT[2048];                     // transposed stft: [m*32 + l]

// ---- smem layout for mma kernel (float offsets) ----
#define XS_LEN  336       // raw x window: 2*127 + 79 = 333, padded
#define A_LDM   16        // no pad: 64 B rows (cp.async 16B-aligned)
#define B_LDM   20
#define MROWS   256
#define A_BUF   (MROWS * A_LDM)     // 4096 floats per stage
#define B_BUF   (NT * B_LDM)        // 1600 floats per buffer
#define NSTAGE  3
#define OFF_XS  0
#define OFF_A   (OFF_XS + XS_LEN)              // 3 stages
#define OFF_B   (OFF_A + NSTAGE * A_BUF)       // 2 buffers
#define SM_FLOATS (OFF_B + 2 * B_BUF)          // 15824 floats = 63296 B

// round-to-nearest tf32 (used for the X operand only; W relies on the
// tensor core's implicit fp32->tf32 truncation)
__device__ __forceinline__ float rt32(float w) {
    float r;
    asm("cvt.rna.tf32.f32 %0, %1;" : "=f"(r) : "f"(w));
    return r;
}
__device__ __forceinline__ unsigned smem_u32(const void* p) {
    return (unsigned)__cvta_generic_to_shared(p);
}
__device__ __forceinline__ void cp_async16(unsigned dst, const void* src) {
    asm volatile("cp.async.cg.shared.global [%0], [%1], 16;" :: "r"(dst), "l"(src));
}
#define CP_COMMIT()  asm volatile("cp.async.commit_group;")
#define CP_WAIT1()   asm volatile("cp.async.wait_group 1;")

// ============================================================================
// Kernel 1: wmma tf32 split-K GEMM partials (single product: D = W * Xh)
//   Tpart[ks][b][o][t] = sum_{k in 128-chunk} W[o,k] * Xh[b,ci,2q+t]
// Grid (2 mtile, 4 batch, 32 ks) = 256 CTAs, 256 thr (8 warps), 2 CTA/SM.
// A staged straight from conv_w via 3-stage cp.async (tensor core truncates
// fp32->tf32 internally); B built RN-rounded from the x window; ONE barrier
// per tile. CTA (0,0,0) additionally builds the transposed stft table g_swT
// (consumed only by the next kernel — ordered by the kernel boundary).
// ============================================================================
__global__ __launch_bounds__(256, 2)
void mma_kernel(const float* __restrict__ x,
                const float* __restrict__ conv_w,
                const float* __restrict__ stft_w) {
    extern __shared__ __align__(16) float sm[];
    float* xs = sm + OFF_XS;

    const int tid = threadIdx.x, wid = tid >> 5;
    const int mtile = blockIdx.x;           // 0..1
    const int b     = blockIdx.y;           // 0..3
    const int ks    = blockIdx.z;           // 0..31
    const int ci    = ks >> 4;
    const int q0    = (ks & 15) * 128;

    const float* srcH = conv_w + (size_t)(mtile * MROWS) * 4096 + ks * 128;

    // ---- prologue: cp.async A stages 0 and 1 ----
    #pragma unroll
    for (int pt = 0; pt < 2; pt++) {
        float* AB = sm + OFF_A + pt * A_BUF;
        #pragma unroll
        for (int j = 0; j < 4; j++) {
            int i = tid + j * 256;               // 0..1023
            int r = i >> 2, c4 = (i & 3) * 4;
            cp_async16(smem_u32(AB + r * A_LDM + c4),
                       srcH + (size_t)r * 4096 + pt * KTILE + c4);
        }
        CP_COMMIT();
    }

    // ---- one CTA builds the transposed stft table (overlaps cp.async) ----
    if (mtile == 0 && b == 0 && ks == 0) {
        #pragma unroll
        for (int j = 0; j < 8; j++) {
            int i = tid + j * 256;               // 0..2047
            int l = i >> 6, m = i & 63;
            g_swT[m * 32 + l] = stft_w[i];
        }
    }

    // ---- stage raw x window, then build B[0] ----
    const float* xrow = x + (b * CCH + ci) * SLEN;
    for (int j = tid; j < XS_LEN; j += 256) {
        int g = 2 * q0 + j;
        xs[j] = (g < SLEN) ? xrow[g] : 0.0f;
    }
    __syncthreads();   // xs published
    {
        float* B0 = sm + OFF_B;
        #pragma unroll
        for (int j = 0; j < 5; j++) {
            int i = tid + j * 256;               // 0..1279
            int tt = i >> 4, kk = i & 15;
            B0[tt * B_LDM + kk] = rt32(xs[2 * kk + tt]);
        }
    }

    wmma::fragment<wmma::accumulator, 16, 16, 8, float> c[2][5];
    #pragma unroll
    for (int i = 0; i < 2; i++)
        #pragma unroll
        for (int n = 0; n < 5; n++) wmma::fill_fragment(c[i][n], 0.0f);

    #pragma unroll 1
    for (int t = 0; t < NTILES; t++) {
        const int stg  = t % NSTAGE;
        const int bbuf = t & 1;

        CP_WAIT1();        // A[t] staging complete (issuing-thread view)
        __syncthreads();   // publish A[t] + B[t]; all warps past t-1 MMAs

        // issue A[t+2] into stage (t+2)%3 (tile t-1's stage — safe)
        if (t + 2 < NTILES) {
            float* AN = sm + OFF_A + ((t + 2) % NSTAGE) * A_BUF;
            #pragma unroll
            for (int j = 0; j < 4; j++) {
                int i = tid + j * 256;
                int r = i >> 2, c4 = (i & 3) * 4;
                cp_async16(smem_u32(AN + r * A_LDM + c4),
                           srcH + (size_t)r * 4096 + (t + 2) * KTILE + c4);
            }
        }
        CP_COMMIT();       // commit every iteration (wait_group count exact)

        // build B[t+1] into buf (t+1)&1 (tile t-1's buf — safe)
        if (t + 1 < NTILES) {
            float* Bn = sm + OFF_B + ((t + 1) & 1) * B_BUF;
            #pragma unroll
            for (int j = 0; j < 5; j++) {
                int i = tid + j * 256;
                int tt = i >> 4, kk = i & 15;
                Bn[tt * B_LDM + kk] = rt32(xs[2 * ((t + 1) * KTILE + kk) + tt]);
            }
        }

        // ---- MMAs on tile t: D += W * Xh ----
        const float* aH = sm + OFF_A + stg * A_BUF + (wid * 32) * A_LDM;
        const float* Bt = sm + OFF_B + bbuf * B_BUF;
        #pragma unroll
        for (int k8 = 0; k8 < KTILE / 8; k8++) {
            wmma::fragment<wmma::matrix_a, 16, 16, 8, wmma::precision::tf32,
                           wmma::row_major> fah0, fah1;
            wmma::load_matrix_sync(fah0, aH + k8 * 8, A_LDM);
            wmma::load_matrix_sync(fah1, aH + 16 * A_LDM + k8 * 8, A_LDM);
            #pragma unroll
            for (int n = 0; n < 5; n++) {
                wmma::fragment<wmma::matrix_b, 16, 16, 8, wmma::precision::tf32,
                               wmma::col_major> fbh;
                wmma::load_matrix_sync(fbh, Bt + n * 16 * B_LDM + k8 * 8, B_LDM);
                wmma::mma_sync(c[0][n], fah0, fbh, c[0][n]);
                wmma::mma_sync(c[1][n], fah1, fbh, c[1][n]);
            }
        }
    }

    // ---- store partials: Tpart[ks][b][o][t80], row-major ldm=80 ----
    float* dst = g_Tpart + (((size_t)ks * BQ + b) * OUTC
                            + mtile * MROWS + wid * 32) * NT;
    #pragma unroll
    for (int i = 0; i < 2; i++)
        #pragma unroll
        for (int n = 0; n < 5; n++)
            wmma::store_matrix_sync(dst + i * 16 * NT + n * 16, c[i][n],
                                    NT, wmma::mem_row_major);
}

// ============================================================================
// Kernel 2: FUSED split-K reduce + epilogue.
// Phase 1: block sums its 4x72 T values over 32 ks partials (coalesced L2).
// Phase 2: out[b,o, p*2048 + m*32 + l] = relu( swT[m,l]*T[b,o,p+m] + bias )
// ============================================================================
#define BO_PER_BLK 4
__global__ __launch_bounds__(256)
void epilogue_kernel(const float* __restrict__ conv_b,
                     float* __restrict__ out) {
    __shared__ float Ts[BO_PER_BLK * TDIM];     // 288
    __shared__ float biasS[BO_PER_BLK];

    const int bo0 = blockIdx.x * BO_PER_BLK;
    const int b   = bo0 >> 9;
    const int o0  = bo0 & (OUTC - 1);
    const int tid = threadIdx.x;

    // hoisted sw loads — issued first, overlap the phase-1 reduction
    float4 sw[4];
    int   pm[4];
    #pragma unroll
    for (int it = 0; it < 4; it++) {
        int q  = tid + it * 256;      // quad index; s' = 4*q
        int sp = q * 4;
        int p  = sp >> 11;
        int m  = (sp >> 5) & 63;
        int l0 = sp & 31;
        pm[it] = p + m;
        sw[it] = __ldg((const float4*)&g_swT[m * 32 + l0]);
    }
    if (tid < BO_PER_BLK)
        biasS[tid] = conv_b[o0 + tid];

    // phase 1: split-K reduce for this block's 288 T values
    for (int j = tid; j < BO_PER_BLK * TDIM; j += 256) {
        int jb = j / TDIM, t = j - jb * TDIM;
        const float* src = g_Tpart + ((size_t)b * OUTC + o0 + jb) * NT + t;
        float s = 0.0f;
        #pragma unroll 8
        for (int ks = 0; ks < KCH; ks++)
            s += src[(size_t)ks * (BQ * OUTC * NT)];
        Ts[j] = s;
    }
    __syncthreads();

    // phase 2: expand + relu + store
    #pragma unroll
    for (int jb = 0; jb < BO_PER_BLK; jb++) {
        const float bias = biasS[jb];
        float4* out4 = (float4*)(out + (size_t)(bo0 + jb) * 4096);
        const float* TsRow = &Ts[jb * TDIM];
        #pragma unroll
        for (int it = 0; it < 4; it++) {
            float tv = TsRow[pm[it]];
            float4 r;
            r.x = fmaxf(fmaf(sw[it].x, tv, bias), 0.0f);
            r.y = fmaxf(fmaf(sw[it].y, tv, bias), 0.0f);
            r.z = fmaxf(fmaf(sw[it].z, tv, bias), 0.0f);
            r.w = fmaxf(fmaf(sw[it].w, tv, bias), 0.0f);
            out4[tid + it * 256] = r;
        }
    }
}

// ============================================================================
extern "C" void kernel_launch(void* const* d_in, const int* in_sizes, int n_in,
                              void* d_out, int out_size) {
    const float* x      = nullptr;
    const float* stft_w = nullptr;
    const float* conv_w = nullptr;
    const float* conv_b = nullptr;
    for (int i = 0; i < n_in; i++) {
        switch (in_sizes[i]) {
            case BQ * CCH * SLEN:  x      = (const float*)d_in[i]; break;  // 32768
            case 32 * 64:          stft_w = (const float*)d_in[i]; break;  // 2048
            case OUTC * 4096:      conv_w = (const float*)d_in[i]; break;  // 2097152
            case OUTC:             conv_b = (const float*)d_in[i]; break;  // 512
        }
    }

    static int smem_set = 0;
    if (!smem_set) {
        cudaFuncSetAttribute(mma_kernel,
                             cudaFuncAttributeMaxDynamicSharedMemorySize,
                             SM_FLOATS * 4);
        smem_set = 1;
    }

    mma_kernel<<<dim3(2, BQ, KCH), 256, SM_FLOATS * 4>>>(x, conv_w, stft_w);
    epilogue_kernel<<<(BQ * OUTC) / BO_PER_BLK, 256>>>(conv_b, (float*)d_out);
}